// round 5
// baseline (speedup 1.0000x reference)
#include <cuda_runtime.h>

// LIF neuron forward: X [B=64, T=32, N=65536] f32 -> spikes, same shape.
// Recurrence per (b,n): mem = mem + (x - mem)/TAU (TAU=0.5); spike = mem > 1;
// mem = spike ? 0 : mem.  Pure HBM-bound streaming kernel.
//
// R4: 161.9us, DRAM 84.0% (6657 GB/s), rel_err 0.0.
// R5 change: __ldcs / __stcs streaming cache hints (evict-first) — input is
// read-once, output is write-once; avoid L2 thrash between the two 512MiB
// streams to improve DRAM read/write turnaround.
// fmaf(x-m, 2, m) is bit-identical to the reference's unfused form
// because *2 is exact in fp32; spike decisions cannot flip.

namespace {
constexpr int B  = 64;
constexpr int T  = 32;
constexpr int N  = 65536;
constexpr int N4 = N / 4;                 // float4 lanes per (b,t) row: 16384
constexpr float VTH = 1.0f;
}

__global__ __launch_bounds__(256, 8)
void lif_kernel(const float4* __restrict__ X, float4* __restrict__ out) {
    const unsigned idx = blockIdx.x * 256u + threadIdx.x;   // 0 .. B*N4-1
    const unsigned b = idx >> 14;          // idx / N4   (N4 = 2^14)
    const unsigned n = idx & (N4 - 1);     // idx % N4

    const size_t base = (size_t)b * (size_t)T * (size_t)N4 + n;
    const float4* __restrict__ xp = X + base;
    float4* __restrict__ op = out + base;

    float m0 = 0.f, m1 = 0.f, m2 = 0.f, m3 = 0.f;

#pragma unroll
    for (int t = 0; t < T; ++t) {
        const float4 x = __ldcs(xp + (size_t)t * N4);   // streaming load, evict-first

        // mem = mem + (x - mem) * 2  -- rounding order matches reference
        m0 = fmaf(x.x - m0, 2.0f, m0);
        m1 = fmaf(x.y - m1, 2.0f, m1);
        m2 = fmaf(x.z - m2, 2.0f, m2);
        m3 = fmaf(x.w - m3, 2.0f, m3);

        const bool s0 = m0 > VTH;
        const bool s1 = m1 > VTH;
        const bool s2 = m2 > VTH;
        const bool s3 = m3 > VTH;

        float4 sp;
        sp.x = s0 ? 1.0f : 0.0f;
        sp.y = s1 ? 1.0f : 0.0f;
        sp.z = s2 ? 1.0f : 0.0f;
        sp.w = s3 ? 1.0f : 0.0f;

        m0 = s0 ? 0.0f : m0;
        m1 = s1 ? 0.0f : m1;
        m2 = s2 ? 0.0f : m2;
        m3 = s3 ? 0.0f : m3;

        __stcs(op + (size_t)t * N4, sp);                // streaming store, evict-first
    }
}

extern "C" void kernel_launch(void* const* d_in, const int* in_sizes, int n_in,
                              void* d_out, int out_size) {
    (void)in_sizes; (void)n_in; (void)out_size;
    const float4* X = (const float4*)d_in[0];
    float4* out = (float4*)d_out;

    const int total_threads = B * N4;          // 1,048,576
    const int block = 256;
    const int grid = total_threads / block;    // 4096
    lif_kernel<<<grid, block>>>(X, out);
}

// round 6
// speedup vs baseline: 1.0304x; 1.0304x over previous
#include <cuda_runtime.h>

// LIF neuron forward: X [B=64, T=32, N=65536] f32 -> spikes, same shape.
// Recurrence per (b,n): mem = mem + (x - mem)/TAU (TAU=0.5); spike = mem > 1;
// mem = spike ? 0 : mem.  Pure HBM-bound streaming kernel.
//
// R4: plain loads, __launch_bounds__(256,8) regs=32 -> 161.9us, DRAM 84.0%.
// R5: __ldcs/__stcs -> regs 20, MLP collapsed, 165.0us / 80.4%. REVERTED.
// R6 change: keep plain loads; relax launch bounds to (256,6) -> reg cap 40,
// letting ptxas batch a deeper LDG.E.128 window (higher per-thread MLP).
// Need ~115 outstanding lines/SM to cover 577cyc DRAM latency at 6.7TB/s.
//
// fmaf(x-m, 2, m) is bit-identical to the reference's unfused form
// because *2 is exact in fp32; spike decisions cannot flip.

namespace {
constexpr int B  = 64;
constexpr int T  = 32;
constexpr int N  = 65536;
constexpr int N4 = N / 4;                 // float4 lanes per (b,t) row: 16384
constexpr float VTH = 1.0f;
}

__global__ __launch_bounds__(256, 6)
void lif_kernel(const float4* __restrict__ X, float4* __restrict__ out) {
    const unsigned idx = blockIdx.x * 256u + threadIdx.x;   // 0 .. B*N4-1
    const unsigned b = idx >> 14;          // idx / N4   (N4 = 2^14)
    const unsigned n = idx & (N4 - 1);     // idx % N4

    const size_t base = (size_t)b * (size_t)T * (size_t)N4 + n;
    const float4* __restrict__ xp = X + base;
    float4* __restrict__ op = out + base;

    float m0 = 0.f, m1 = 0.f, m2 = 0.f, m3 = 0.f;

#pragma unroll
    for (int t = 0; t < T; ++t) {
        const float4 x = xp[(size_t)t * N4];

        // mem = mem + (x - mem) * 2  -- rounding order matches reference
        m0 = fmaf(x.x - m0, 2.0f, m0);
        m1 = fmaf(x.y - m1, 2.0f, m1);
        m2 = fmaf(x.z - m2, 2.0f, m2);
        m3 = fmaf(x.w - m3, 2.0f, m3);

        const bool s0 = m0 > VTH;
        const bool s1 = m1 > VTH;
        const bool s2 = m2 > VTH;
        const bool s3 = m3 > VTH;

        float4 sp;
        sp.x = s0 ? 1.0f : 0.0f;
        sp.y = s1 ? 1.0f : 0.0f;
        sp.z = s2 ? 1.0f : 0.0f;
        sp.w = s3 ? 1.0f : 0.0f;

        m0 = s0 ? 0.0f : m0;
        m1 = s1 ? 0.0f : m1;
        m2 = s2 ? 0.0f : m2;
        m3 = s3 ? 0.0f : m3;

        op[(size_t)t * N4] = sp;
    }
}

extern "C" void kernel_launch(void* const* d_in, const int* in_sizes, int n_in,
                              void* d_out, int out_size) {
    (void)in_sizes; (void)n_in; (void)out_size;
    const float4* X = (const float4*)d_in[0];
    float4* out = (float4*)d_out;

    const int total_threads = B * N4;          // 1,048,576
    const int block = 256;
    const int grid = total_threads / block;    // 4096
    lif_kernel<<<grid, block>>>(X, out);
}